// round 7
// baseline (speedup 1.0000x reference)
#include <cuda_runtime.h>

// Shape: [1, 8, 8, 8, 258, 258, 1] fp32; total = 34,080,768 elems = 8,520,192 float4.
//
// R6 permute scheme + 2 chunks per thread. Chunk pair (i, i+HALF4) where
// HALF4*4 elems = 17,040,384 = EXACTLY 256 images, so both chunks share the
// same (h, w) -> one div/mod + one predicate set serves both. 4 front-batched
// LDG.128 per thread (MLP x2), half the index math per byte.
//
// Remap recap (258 % 4 == 2):
//   w0==0   : lane0 <- v.y            w0==254 : lane3 <- v.z
//   w0==256 (straddle): lane1 <- v.x, lane2 <- v.w
//   rows h==0 / 257 (and straddle into 257): per-lane scalar loads at
//   idx+k+delta (delta = +-1 w-edge w/ original h, +-258 h-edge).

#define HW        258
#define IMG_ELEMS 66564u      // 258*258
#define TOTAL4    8520192u
#define HALF4     4260096u    // chunks; *4 elems = 256 whole images
#define OFFS      17040384u   // element offset of second half

__global__ __launch_bounds__(256)
void halo_f4x2_kernel(const float* __restrict__ x,
                      const float4* __restrict__ hm,
                      float4* __restrict__ out)
{
    unsigned i = blockIdx.x * 256u + threadIdx.x;   // [0, HALF4) exact
    unsigned idx = i * 4u;

    // Front-batch all 4 vector loads (MLP).
    float4 vA = __ldcs(reinterpret_cast<const float4*>(x + idx));
    float4 vB = __ldcs(reinterpret_cast<const float4*>(x + idx + OFFS));
    float4 bA = __ldcs(hm + i);
    float4 bB = __ldcs(hm + i + HALF4);

    unsigned rem = idx % IMG_ELEMS;
    unsigned h0  = rem / HW;
    unsigned w0  = rem - h0 * HW;   // even, 0..256

    float a0 = vA.x, a1 = vA.y, a2 = vA.z, a3 = vA.w;
    float c0 = vB.x, c1 = vB.y, c2 = vB.z, c3 = vB.w;

    if (h0 == 0u || h0 == HW - 1u || (h0 == HW - 2u && w0 == HW - 2u)) {
        // Slow path (rows touching h-edges): per-lane remapped scalar loads.
        unsigned h = h0, w = w0;
        float lA[4], lB[4];
#pragma unroll
        for (int k = 0; k < 4; ++k) {
            int delta = 0;
            if (w == 0u)           delta = 1;     // w-edge keeps original h
            else if (w == HW - 1u) delta = -1;
            else if (h == 0u)      delta = HW;    // h-edge
            else if (h == HW - 1u) delta = -HW;
            lA[k] = __ldg(x + (int)(idx + k) + delta);
            lB[k] = __ldg(x + (int)(idx + OFFS + k) + delta);
            if (++w == HW) { w = 0u; ++h; }
        }
        a0 = lA[0]; a1 = lA[1]; a2 = lA[2]; a3 = lA[3];
        c0 = lB[0]; c1 = lB[1]; c2 = lB[2]; c3 = lB[3];
    } else {
        // Branchless w-edge permutes (same predicates for both chunks).
        if (w0 == 0u)      { a0 = vA.y;             c0 = vB.y; }
        if (w0 == HW - 4u) { a3 = vA.z;             c3 = vB.z; }
        if (w0 == HW - 2u) { a1 = vA.x; a2 = vA.w;  c1 = vB.x; c2 = vB.w; }
    }

    float4 rA, rB;
    rA.x = a0 * bA.x;  rA.y = a1 * bA.y;  rA.z = a2 * bA.z;  rA.w = a3 * bA.w;
    rB.x = c0 * bB.x;  rB.y = c1 * bB.y;  rB.z = c2 * bB.z;  rB.w = c3 * bB.w;

    __stcs(out + i, rA);
    __stcs(out + i + HALF4, rB);
}

extern "C" void kernel_launch(void* const* d_in, const int* in_sizes, int n_in,
                              void* d_out, int out_size)
{
    const float* x  = (const float*)d_in[0];
    const float* hm = (const float*)d_in[1];
    float* out = (float*)d_out;

    const int threads = 256;
    const int blocks = HALF4 / threads;   // 16,641 exact
    halo_f4x2_kernel<<<blocks, threads>>>(x, (const float4*)hm, (float4*)out);
}